// round 2
// baseline (speedup 1.0000x reference)
#include <cuda_runtime.h>
#include <cuda_fp16.h>

#define BATCH 4
#define NNODE 4096
#define DIM   256
#define OUTC  64
#define NPAD  72          // 64 cols + e col (64) + 7 zero pad -> 9 n-tiles of 8
#define NT    9
#define KSPLIT 4
#define KCH   128

// ---------------- device scratch ----------------
__device__ float g_vsrc[DIM];
__device__ float g_bsum[OUTC];
__device__ __align__(16) uint2 g_B2frag[16 * NT * 32];                  // 36 KB
__device__ __align__(16) uint2 g_Pfrag[(BATCH * NNODE / 16) * NT * 32]; // 2.3 MB
__device__ float g_Cp[(size_t)KSPLIT * BATCH * NNODE * NPAD];           // 75 MB

// ---------------- helpers ----------------
__device__ __forceinline__ unsigned int f2_to_h2(float2 f) {
    __half2 h = __float22half2_rn(f);
    return *reinterpret_cast<unsigned int*>(&h);
}
__device__ __forceinline__ void cp_async8(void* smem_dst, const void* gmem_src) {
    unsigned int s = (unsigned int)__cvta_generic_to_shared(smem_dst);
    asm volatile("cp.async.ca.shared.global [%0], [%1], 8;\n" :: "r"(s), "l"(gmem_src));
}
__device__ __forceinline__ void cp_commit() {
    asm volatile("cp.async.commit_group;\n");
}
template <int N>
__device__ __forceinline__ void cp_wait() {
    asm volatile("cp.async.wait_group %0;\n" :: "n"(N));
}
__device__ __forceinline__ void mma16816(float* acc, unsigned A0, unsigned A1,
                                         unsigned A2, unsigned A3, uint2 bb) {
    asm volatile(
        "mma.sync.aligned.m16n8k16.row.col.f32.f16.f16.f32 "
        "{%0,%1,%2,%3}, {%4,%5,%6,%7}, {%8,%9}, {%0,%1,%2,%3};\n"
        : "+f"(acc[0]), "+f"(acc[1]), "+f"(acc[2]), "+f"(acc[3])
        : "r"(A0), "r"(A1), "r"(A2), "r"(A3), "r"(bb.x), "r"(bb.y));
}

// ---------------- kernel A1: wsrc -> vsrc, bsum ----------------
__global__ void k_prep(const float* __restrict__ Wfc,
                       const float* __restrict__ bfc,
                       const float* __restrict__ Wattn) {
    __shared__ float wsrc[DIM];
    int t = threadIdx.x;                    // 256
    int h = t >> 6, o = t & 63;
    float s = 0.f;
    #pragma unroll
    for (int k = 0; k < 4; k++) s += Wattn[k * 512 + h * 128 + o];
    wsrc[t] = 0.25f * s;
    __syncthreads();
    float v = 0.f;
    for (int m = 0; m < DIM; m++) v += wsrc[m] * Wfc[m * DIM + t];
    g_vsrc[t] = v;
    if (t < OUTC) {
        float a = 0.f;
        #pragma unroll
        for (int hh = 0; hh < 4; hh++) a += bfc[hh * 64 + t];
        g_bsum[t] = a;
    }
}

// ---------------- kernel A2: build B2 = [Wsum | vsrc | 0] fragments ----------------
// B2[d][n] : n<64 -> sum_h Wfc[h*64+n][d] ; n==64 -> vsrc[d] ; else 0
__device__ __forceinline__ float b2v(const float* __restrict__ Wfc, int d, int n) {
    if (n < OUTC)
        return Wfc[n * DIM + d] + Wfc[(64 + n) * DIM + d] +
               Wfc[(128 + n) * DIM + d] + Wfc[(192 + n) * DIM + d];
    if (n == OUTC) return g_vsrc[d];
    return 0.f;
}
__global__ void k_wfrag(const float* __restrict__ Wfc) {
    int kc = blockIdx.x;                    // 16 blocks, 288 threads
    int t = threadIdx.x;
    int nt = t >> 5, lane = t & 31;
    int g = lane >> 2, tg = lane & 3;
    int n = nt * 8 + g, d0 = kc * 16 + tg * 2;
    __half2 p0 = __floats2half2_rn(b2v(Wfc, d0, n),     b2v(Wfc, d0 + 1, n));
    __half2 p1 = __floats2half2_rn(b2v(Wfc, d0 + 8, n), b2v(Wfc, d0 + 9, n));
    uint2 v;
    v.x = *reinterpret_cast<unsigned int*>(&p0);
    v.y = *reinterpret_cast<unsigned int*>(&p1);
    g_B2frag[(kc * NT + nt) * 32 + lane] = v;
}

// ---------------- kernel B: fused h_sum + src + exp -> P fragments ----------------
__global__ void __launch_bounds__(256) k_hp(const float* __restrict__ X) {
    __shared__ __align__(16) char smem[16 * NT * 32 * sizeof(uint2)];   // 36 KB
    uint2* Bf = reinterpret_cast<uint2*>(smem);
    __half* Ps = reinterpret_cast<__half*>(smem);   // reused after mainloop
    int t = threadIdx.x, lane = t & 31, warp = t >> 5;
    int g = lane >> 2, tg = lane & 3;

    for (int i = t; i < 16 * NT * 32; i += 256) Bf[i] = g_B2frag[i];
    __syncthreads();

    int r0 = blockIdx.x * 128 + warp * 16;
    const float* x0 = X + (size_t)(r0 + g) * DIM;
    const float* x1 = x0 + (size_t)8 * DIM;

    float acc[NT][4];
    #pragma unroll
    for (int nt = 0; nt < NT; nt++)
        #pragma unroll
        for (int q = 0; q < 4; q++) acc[nt][q] = 0.f;

    #pragma unroll
    for (int h2 = 0; h2 < 2; h2++) {
        float2 r[8][4];
        #pragma unroll
        for (int ks = 0; ks < 8; ks++) {
            int k0 = h2 * 128 + ks * 16 + tg * 2;
            r[ks][0] = *(const float2*)(x0 + k0);
            r[ks][1] = *(const float2*)(x1 + k0);
            r[ks][2] = *(const float2*)(x0 + k0 + 8);
            r[ks][3] = *(const float2*)(x1 + k0 + 8);
        }
        #pragma unroll
        for (int ks = 0; ks < 8; ks++) {
            unsigned A0 = f2_to_h2(r[ks][0]);
            unsigned A1 = f2_to_h2(r[ks][1]);
            unsigned A2 = f2_to_h2(r[ks][2]);
            unsigned A3 = f2_to_h2(r[ks][3]);
            #pragma unroll
            for (int nt = 0; nt < NT; nt++)
                mma16816(acc[nt], A0, A1, A2, A3,
                         Bf[((h2 * 8 + ks) * NT + nt) * 32 + lane]);
        }
    }
    __syncthreads();            // all warps done reading Bf; smem becomes Ps

    // src is column 64 (nt=8, reg0/reg2 of tg==0 lanes)
    float e0 = __expf(acc[8][0]);
    float e1 = __expf(acc[8][2]);
    e0 = __shfl_sync(0xffffffffu, e0, lane & ~3);
    e1 = __shfl_sync(0xffffffffu, e1, lane & ~3);

    int rl = warp * 16 + g;
    #pragma unroll
    for (int nt = 0; nt < 8; nt++) {
        int c = nt * 8 + tg * 2;
        float bs0 = g_bsum[c], bs1 = g_bsum[c + 1];
        Ps[rl * NPAD + c]           = __float2half(e0 * (acc[nt][0] + bs0));
        Ps[rl * NPAD + c + 1]       = __float2half(e0 * (acc[nt][1] + bs1));
        Ps[(rl + 8) * NPAD + c]     = __float2half(e1 * (acc[nt][2] + bs0));
        Ps[(rl + 8) * NPAD + c + 1] = __float2half(e1 * (acc[nt][3] + bs1));
    }
    {   // cols 64..71: e in col 64, zeros elsewhere
        int c = 64 + tg * 2;
        __half z = __float2half(0.f);
        Ps[rl * NPAD + c]           = (tg == 0) ? __float2half(e0) : z;
        Ps[rl * NPAD + c + 1]       = z;
        Ps[(rl + 8) * NPAD + c]     = (tg == 0) ? __float2half(e1) : z;
        Ps[(rl + 8) * NPAD + c + 1] = z;
    }
    __syncthreads();

    // repack 128 rows -> 8 k-chunks of B fragments
    for (int idx = t; idx < 8 * NT * 32; idx += 256) {
        int kc = idx / (NT * 32);
        int rem = idx - kc * NT * 32;
        int nt = rem >> 5, l2 = rem & 31;
        int g2 = l2 >> 2, tg2 = l2 & 3;
        int jl = kc * 16 + tg2 * 2, n = nt * 8 + g2;
        uint2 v;
        v.x = (unsigned int)__half_as_ushort(Ps[jl * NPAD + n]) |
              ((unsigned int)__half_as_ushort(Ps[(jl + 1) * NPAD + n]) << 16);
        v.y = (unsigned int)__half_as_ushort(Ps[(jl + 8) * NPAD + n]) |
              ((unsigned int)__half_as_ushort(Ps[(jl + 9) * NPAD + n]) << 16);
        g_Pfrag[((size_t)(blockIdx.x * 8 + kc) * NT + nt) * 32 + l2] = v;
    }
}

// ---------------- kernel C: C = adj @ P  (split-K, pipelined fp16 MMA) ----------------
__global__ void __launch_bounds__(256) k_gemm(const float* __restrict__ adj) {
    __shared__ __align__(16) uint2 Bs[2][(KCH / 16) * NT * 32];   // 36 KB
    int t = threadIdx.x, lane = t & 31, warp = t >> 5;
    int g = lane >> 2, tg = lane & 3;
    int b = blockIdx.y, kz = blockIdx.z;
    int r0 = blockIdx.x * 128 + warp * 16;
    int kbase = kz * (NNODE / KSPLIT);      // 1024-wide K slice

    const float* a0 = adj + ((size_t)b * NNODE + r0 + g) * NNODE;
    const float* a1 = a0 + (size_t)8 * NNODE;

    float acc[NT][4];
    #pragma unroll
    for (int nt = 0; nt < NT; nt++)
        #pragma unroll
        for (int q = 0; q < 4; q++) acc[nt][q] = 0.f;

    const uint2* psrc =
        g_Pfrag + (size_t)(b * (NNODE / 16) + kbase / 16) * NT * 32;
    const int CHW = (KCH / 16) * NT * 32;   // 2304 uint2 per chunk

    // stage chunk 0
    for (int i = t; i < CHW; i += 256) cp_async8(&Bs[0][i], psrc + i);
    cp_commit();

    for (int c = 0; c < 8; c++) {
        if (c < 7) {
            const uint2* s = psrc + (size_t)(c + 1) * CHW;
            for (int i = t; i < CHW; i += 256) cp_async8(&Bs[(c + 1) & 1][i], s + i);
            cp_commit();
        }
        // deep preload of adj for this chunk (32 LDG.64 in flight)
        float2 r[8][4];
        #pragma unroll
        for (int ks = 0; ks < 8; ks++) {
            int k0 = kbase + c * KCH + ks * 16 + tg * 2;
            r[ks][0] = *(const float2*)(a0 + k0);
            r[ks][1] = *(const float2*)(a1 + k0);
            r[ks][2] = *(const float2*)(a0 + k0 + 8);
            r[ks][3] = *(const float2*)(a1 + k0 + 8);
        }
        if (c < 7) cp_wait<1>(); else cp_wait<0>();
        __syncthreads();

        #pragma unroll
        for (int ks = 0; ks < 8; ks++) {
            unsigned A0 = f2_to_h2(r[ks][0]);
            unsigned A1 = f2_to_h2(r[ks][1]);
            unsigned A2 = f2_to_h2(r[ks][2]);
            unsigned A3 = f2_to_h2(r[ks][3]);
            #pragma unroll
            for (int nt = 0; nt < NT; nt++)
                mma16816(acc[nt], A0, A1, A2, A3,
                         Bs[c & 1][(ks * NT + nt) * 32 + lane]);
        }
        __syncthreads();
    }

    size_t base = (((size_t)kz * BATCH + b) * NNODE + r0 + g) * NPAD;
    #pragma unroll
    for (int nt = 0; nt < NT; nt++) {
        int c = nt * 8 + tg * 2;
        *(float2*)&g_Cp[base + c] = make_float2(acc[nt][0], acc[nt][1]);
        *(float2*)&g_Cp[base + (size_t)8 * NPAD + c] =
            make_float2(acc[nt][2], acc[nt][3]);
    }
}

// ---------------- kernel D: reduce split-K, normalize ----------------
__global__ void k_out(float* __restrict__ out) {
    int idx = blockIdx.x * 256 + threadIdx.x;   // < 4*4096*64
    int l = idx & 63;
    int rowflat = idx >> 6;
    float num = 0.f, den = 0.f;
    #pragma unroll
    for (int z = 0; z < KSPLIT; z++) {
        size_t base = ((size_t)z * BATCH * NNODE + rowflat) * NPAD;
        num += g_Cp[base + l];
        den += g_Cp[base + 64];
    }
    out[idx] = num / (den * (float)NNODE);
}

// ---------------- launch ----------------
extern "C" void kernel_launch(void* const* d_in, const int* in_sizes, int n_in,
                              void* d_out, int out_size) {
    const float* X     = (const float*)d_in[0];
    const float* adj   = (const float*)d_in[1];
    const float* Wfc   = (const float*)d_in[2];
    const float* bfc   = (const float*)d_in[3];
    const float* Wattn = (const float*)d_in[4];
    float* out = (float*)d_out;
    (void)in_sizes; (void)n_in; (void)out_size;

    k_prep<<<1, 256>>>(Wfc, bfc, Wattn);
    k_wfrag<<<16, 288>>>(Wfc);
    k_hp<<<BATCH * NNODE / 128, 256>>>(X);
    dim3 ge(NNODE / 128, BATCH, KSPLIT);
    k_gemm<<<ge, 256>>>(adj);
    k_out<<<BATCH * NNODE * OUTC / 256, 256>>>(out);
}

// round 8
// speedup vs baseline: 1.7317x; 1.7317x over previous
#include <cuda_runtime.h>
#include <cuda_fp16.h>

#define BATCH 4
#define NNODE 4096
#define DIM   256
#define OUTC  64
#define NPAD  72          // 64 cols + e col (64) + 7 zero pad -> 9 n-tiles of 8
#define NT    9
#define KSPLIT 2
#define KCH   128

// ---------------- device scratch ----------------
__device__ float g_vsrc[DIM];
__device__ float g_bsum[OUTC];
__device__ __align__(16) uint2 g_B2frag[16 * NT * 32];                  // 36 KB
__device__ __align__(16) uint2 g_Pfrag[(BATCH * NNODE / 16) * NT * 32]; // 2.3 MB
__device__ float g_Cp[(size_t)KSPLIT * BATCH * NNODE * NPAD];           // 9.4 MB

// ---------------- helpers ----------------
// sigma-permuted fragment convention (k within each k16 tile):
//   lane tg owns k = {4tg, 4tg+1} (low pair) and {4tg+2, 4tg+3} (high pair).
// Applied identically to A loads and B packing -> result unchanged.
__device__ __forceinline__ unsigned int h2(float a, float b) {
    __half2 h = __floats2half2_rn(a, b);   // a -> low 16 bits
    return *reinterpret_cast<unsigned int*>(&h);
}
__device__ __forceinline__ void cp_async8(void* smem_dst, const void* gmem_src) {
    unsigned int s = (unsigned int)__cvta_generic_to_shared(smem_dst);
    asm volatile("cp.async.ca.shared.global [%0], [%1], 8;\n" :: "r"(s), "l"(gmem_src));
}
__device__ __forceinline__ void cp_commit() {
    asm volatile("cp.async.commit_group;\n");
}
template <int N>
__device__ __forceinline__ void cp_wait() {
    asm volatile("cp.async.wait_group %0;\n" :: "n"(N));
}
__device__ __forceinline__ void mma16816(float* acc, unsigned A0, unsigned A1,
                                         unsigned A2, unsigned A3, uint2 bb) {
    asm volatile(
        "mma.sync.aligned.m16n8k16.row.col.f32.f16.f16.f32 "
        "{%0,%1,%2,%3}, {%4,%5,%6,%7}, {%8,%9}, {%0,%1,%2,%3};\n"
        : "+f"(acc[0]), "+f"(acc[1]), "+f"(acc[2]), "+f"(acc[3])
        : "r"(A0), "r"(A1), "r"(A2), "r"(A3), "r"(bb.x), "r"(bb.y));
}

// ---------------- kernel A1: wsrc -> vsrc, bsum ----------------
__global__ void k_prep(const float* __restrict__ Wfc,
                       const float* __restrict__ bfc,
                       const float* __restrict__ Wattn) {
    __shared__ float wsrc[DIM];
    int t = threadIdx.x;                    // 256
    int h = t >> 6, o = t & 63;
    float s = 0.f;
    #pragma unroll
    for (int k = 0; k < 4; k++) s += Wattn[k * 512 + h * 128 + o];
    wsrc[t] = 0.25f * s;
    __syncthreads();
    float v = 0.f;
    for (int m = 0; m < DIM; m++) v += wsrc[m] * Wfc[m * DIM + t];
    g_vsrc[t] = v;
    if (t < OUTC) {
        float a = 0.f;
        #pragma unroll
        for (int hh = 0; hh < 4; hh++) a += bfc[hh * 64 + t];
        g_bsum[t] = a;
    }
}

// ---------------- kernel A2: B2 = [Wsum | vsrc | 0] fragments (sigma layout) ----------------
__device__ __forceinline__ float b2v(const float* __restrict__ Wfc, int d, int n) {
    if (n < OUTC)
        return Wfc[n * DIM + d] + Wfc[(64 + n) * DIM + d] +
               Wfc[(128 + n) * DIM + d] + Wfc[(192 + n) * DIM + d];
    if (n == OUTC) return g_vsrc[d];
    return 0.f;
}
__global__ void k_wfrag(const float* __restrict__ Wfc) {
    int kc = blockIdx.x;                    // 16 blocks, 288 threads
    int t = threadIdx.x;
    int nt = t >> 5, lane = t & 31;
    int g = lane >> 2, tg = lane & 3;
    int n = nt * 8 + g, d0 = kc * 16 + tg * 4;
    uint2 v;
    v.x = h2(b2v(Wfc, d0, n),     b2v(Wfc, d0 + 1, n));
    v.y = h2(b2v(Wfc, d0 + 2, n), b2v(Wfc, d0 + 3, n));
    g_B2frag[(kc * NT + nt) * 32 + lane] = v;
}

// ---------------- kernel B: fused h_sum + src + exp -> P fragments ----------------
// 128 threads / 4 warps / 64 rows per CTA
__global__ void __launch_bounds__(128) k_hp(const float* __restrict__ X) {
    __shared__ __align__(16) char smem[16 * NT * 32 * sizeof(uint2)];   // 36 KB
    uint2* Bf = reinterpret_cast<uint2*>(smem);
    __half* Ps = reinterpret_cast<__half*>(smem);   // reused after mainloop
    int t = threadIdx.x, lane = t & 31, warp = t >> 5;
    int g = lane >> 2, tg = lane & 3;

    for (int i = t; i < 16 * NT * 32; i += 128) Bf[i] = g_B2frag[i];
    __syncthreads();

    int r0 = blockIdx.x * 64 + warp * 16;
    const float* x0 = X + (size_t)(r0 + g) * DIM;
    const float* x1 = x0 + (size_t)8 * DIM;

    float acc[NT][4];
    #pragma unroll
    for (int nt = 0; nt < NT; nt++)
        #pragma unroll
        for (int q = 0; q < 4; q++) acc[nt][q] = 0.f;

    #pragma unroll
    for (int hh = 0; hh < 2; hh++) {
        float4 q0[8], q1[8];
        #pragma unroll
        for (int ks = 0; ks < 8; ks++) {
            int k0 = hh * 128 + ks * 16 + tg * 4;
            q0[ks] = *(const float4*)(x0 + k0);
            q1[ks] = *(const float4*)(x1 + k0);
        }
        #pragma unroll
        for (int ks = 0; ks < 8; ks++) {
            unsigned A0 = h2(q0[ks].x, q0[ks].y);
            unsigned A1 = h2(q1[ks].x, q1[ks].y);
            unsigned A2 = h2(q0[ks].z, q0[ks].w);
            unsigned A3 = h2(q1[ks].z, q1[ks].w);
            #pragma unroll
            for (int nt = 0; nt < NT; nt++)
                mma16816(acc[nt], A0, A1, A2, A3,
                         Bf[((hh * 8 + ks) * NT + nt) * 32 + lane]);
        }
    }
    __syncthreads();            // done with Bf; smem becomes Ps

    // src column 64 lives in tg==0 lanes of n-tile 8 (acc[8][0]: row g, acc[8][2]: row g+8)
    float e0 = __expf(acc[8][0]);
    float e1 = __expf(acc[8][2]);
    e0 = __shfl_sync(0xffffffffu, e0, lane & ~3);
    e1 = __shfl_sync(0xffffffffu, e1, lane & ~3);

    int rl = warp * 16 + g;
    #pragma unroll
    for (int nt = 0; nt < 8; nt++) {
        int c = nt * 8 + tg * 2;
        float bs0 = g_bsum[c], bs1 = g_bsum[c + 1];
        Ps[rl * NPAD + c]           = __float2half(e0 * (acc[nt][0] + bs0));
        Ps[rl * NPAD + c + 1]       = __float2half(e0 * (acc[nt][1] + bs1));
        Ps[(rl + 8) * NPAD + c]     = __float2half(e1 * (acc[nt][2] + bs0));
        Ps[(rl + 8) * NPAD + c + 1] = __float2half(e1 * (acc[nt][3] + bs1));
    }
    {   // cols 64..71: e in col 64, zeros elsewhere
        int c = 64 + tg * 2;
        __half z = __float2half(0.f);
        Ps[rl * NPAD + c]           = (tg == 0) ? __float2half(e0) : z;
        Ps[rl * NPAD + c + 1]       = z;
        Ps[(rl + 8) * NPAD + c]     = (tg == 0) ? __float2half(e1) : z;
        Ps[(rl + 8) * NPAD + c + 1] = z;
    }
    __syncthreads();

    // repack 64 rows -> 4 k-chunks of sigma-layout B fragments
    for (int idx = t; idx < 4 * NT * 32; idx += 128) {
        int kc = idx / (NT * 32);
        int rem = idx - kc * NT * 32;
        int nt = rem >> 5, l2 = rem & 31;
        int g2 = l2 >> 2, tg2 = l2 & 3;
        int jl = kc * 16 + tg2 * 4, n = nt * 8 + g2;
        uint2 v;
        v.x = (unsigned int)__half_as_ushort(Ps[jl * NPAD + n]) |
              ((unsigned int)__half_as_ushort(Ps[(jl + 1) * NPAD + n]) << 16);
        v.y = (unsigned int)__half_as_ushort(Ps[(jl + 2) * NPAD + n]) |
              ((unsigned int)__half_as_ushort(Ps[(jl + 3) * NPAD + n]) << 16);
        g_Pfrag[((size_t)(blockIdx.x * 4 + kc) * NT + nt) * 32 + l2] = v;
    }
}

// ---------------- kernel C: C = adj @ P  (split-K, pipelined fp16 MMA) ----------------
__global__ void __launch_bounds__(256) k_gemm(const float* __restrict__ adj) {
    __shared__ __align__(16) uint2 Bs[2][(KCH / 16) * NT * 32];   // 36 KB
    int t = threadIdx.x, lane = t & 31, warp = t >> 5;
    int g = lane >> 2, tg = lane & 3;
    int b = blockIdx.y, kz = blockIdx.z;
    int r0 = blockIdx.x * 128 + warp * 16;
    int kbase = kz * (NNODE / KSPLIT);      // 2048-wide K slice
    const int NCHUNK = (NNODE / KSPLIT) / KCH;  // 16

    const float* a0 = adj + ((size_t)b * NNODE + r0 + g) * NNODE;
    const float* a1 = a0 + (size_t)8 * NNODE;

    float acc[NT][4];
    #pragma unroll
    for (int nt = 0; nt < NT; nt++)
        #pragma unroll
        for (int q = 0; q < 4; q++) acc[nt][q] = 0.f;

    const uint2* psrc =
        g_Pfrag + (size_t)(b * (NNODE / 16) + kbase / 16) * NT * 32;
    const int CHW = (KCH / 16) * NT * 32;   // 2304 uint2 per chunk

    for (int i = t; i < CHW; i += 256) cp_async8(&Bs[0][i], psrc + i);
    cp_commit();

    for (int c = 0; c < NCHUNK; c++) {
        if (c < NCHUNK - 1) {
            const uint2* s = psrc + (size_t)(c + 1) * CHW;
            for (int i = t; i < CHW; i += 256) cp_async8(&Bs[(c + 1) & 1][i], s + i);
            cp_commit();
        }
        // deep preload of adj: 16 LDG.128 in flight per thread
        float4 q0[8], q1[8];
        #pragma unroll
        for (int ks = 0; ks < 8; ks++) {
            int k0 = kbase + c * KCH + ks * 16 + tg * 4;
            q0[ks] = *(const float4*)(a0 + k0);
            q1[ks] = *(const float4*)(a1 + k0);
        }
        if (c < NCHUNK - 1) cp_wait<1>(); else cp_wait<0>();
        __syncthreads();

        #pragma unroll
        for (int ks = 0; ks < 8; ks++) {
            unsigned A0 = h2(q0[ks].x, q0[ks].y);
            unsigned A1 = h2(q1[ks].x, q1[ks].y);
            unsigned A2 = h2(q0[ks].z, q0[ks].w);
            unsigned A3 = h2(q1[ks].z, q1[ks].w);
            #pragma unroll
            for (int nt = 0; nt < NT; nt++)
                mma16816(acc[nt], A0, A1, A2, A3,
                         Bs[c & 1][(ks * NT + nt) * 32 + lane]);
        }
        __syncthreads();
    }

    // epilogue: smem transpose -> fully coalesced STG
    float* Cs = reinterpret_cast<float*>(&Bs[0][0]);   // 36.9 KB region
    int row = warp * 16 + g;
    #pragma unroll
    for (int nt = 0; nt < NT; nt++) {
        int c = nt * 8 + tg * 2;
        Cs[row * NPAD + c]           = acc[nt][0];
        Cs[row * NPAD + c + 1]       = acc[nt][1];
        Cs[(row + 8) * NPAD + c]     = acc[nt][2];
        Cs[(row + 8) * NPAD + c + 1] = acc[nt][3];
    }
    __syncthreads();
    size_t outbase =
        (((size_t)kz * BATCH + b) * NNODE + (size_t)blockIdx.x * 128) * NPAD;
    float4* dst = reinterpret_cast<float4*>(g_Cp + outbase);
    const float4* srcp = reinterpret_cast<const float4*>(Cs);
    #pragma unroll
    for (int i = t; i < 128 * NPAD / 4; i += 256) dst[i] = srcp[i];
}

// ---------------- kernel D: reduce split-K, normalize ----------------
__global__ void k_out(float* __restrict__ out) {
    int idx = blockIdx.x * 256 + threadIdx.x;   // < 4*4096*64
    int l = idx & 63;
    int rowflat = idx >> 6;
    float num = 0.f, den = 0.f;
    #pragma unroll
    for (int z = 0; z < KSPLIT; z++) {
        size_t base = ((size_t)z * BATCH * NNODE + rowflat) * NPAD;
        num += g_Cp[base + l];
        den += g_Cp[base + 64];
    }
    out[idx] = num / (den * (float)NNODE);
}

// ---------------- launch ----------------
extern "C" void kernel_launch(void* const* d_in, const int* in_sizes, int n_in,
                              void* d_out, int out_size) {
    const float* X     = (const float*)d_in[0];
    const float* adj   = (const float*)d_in[1];
    const float* Wfc   = (const float*)d_in[2];
    const float* bfc   = (const float*)d_in[3];
    const float* Wattn = (const float*)d_in[4];
    float* out = (float*)d_out;
    (void)in_sizes; (void)n_in; (void)out_size;

    k_prep<<<1, 256>>>(Wfc, bfc, Wattn);
    k_wfrag<<<16, 288>>>(Wfc);
    k_hp<<<BATCH * NNODE / 64, 128>>>(X);
    dim3 ge(NNODE / 128, BATCH, KSPLIT);
    k_gemm<<<ge, 256>>>(adj);
    k_out<<<BATCH * NNODE * OUTC / 256, 256>>>(out);
}